// round 3
// baseline (speedup 1.0000x reference)
#include <cuda_runtime.h>

#define E_NUM 32000
#define NODES 1600
#define CCH 128
#define M0C 7
#define NSPH 49
#define NALL 29
#define BASIS 512
#define HID 128
#define DIN 768
#define W3N 896
#define WROW (NSPH*NALL)   /* 1421 */

// ---------------- scratch (device globals: allocation-free) ----------------
__device__ float g_h1[(size_t)E_NUM * HID];
__device__ float g_h2[(size_t)E_NUM * HID];
__device__ float g_x0[(size_t)E_NUM * W3N];
__device__ int   g_count[NODES];
__device__ int   g_off[NODES + 1];
__device__ int   g_cursor[NODES];
__device__ int   g_edges[E_NUM];
__device__ int   g_pos[M0C];

// ---------------- CSR build ----------------
__global__ void k_zero() {
    int i = blockIdx.x * 256 + threadIdx.x;
    if (i < NODES) { g_count[i] = 0; g_cursor[i] = 0; }
}

__global__ void k_hist(const int* __restrict__ eidx) {
    int e = blockIdx.x * 256 + threadIdx.x;
    if (e < E_NUM) atomicAdd(&g_count[eidx[E_NUM + e]], 1);
}

__global__ void k_prep(const float* __restrict__ tom) {
    __shared__ int csum[256];
    int tid = threadIdx.x;
    if (tid < M0C) {
        int p = 0;
        for (int j = 0; j < NALL; j++)
            if (tom[tid * NALL + j] > 0.5f) p = j;
        g_pos[tid] = p;
    }
    int base = tid * 7;
    int s = 0;
    for (int i = 0; i < 7; i++) {
        int idx = base + i;
        if (idx < NODES) s += g_count[idx];
    }
    csum[tid] = s;
    __syncthreads();
    if (tid == 0) {
        int run = 0;
        for (int i = 0; i < 256; i++) { int t = csum[i]; csum[i] = run; run += t; }
        g_off[NODES] = run;
    }
    __syncthreads();
    int run = csum[tid];
    for (int i = 0; i < 7; i++) {
        int idx = base + i;
        if (idx < NODES) { g_off[idx] = run; run += g_count[idx]; }
    }
}

__global__ void k_scatter(const int* __restrict__ eidx) {
    int e = blockIdx.x * 256 + threadIdx.x;
    if (e < E_NUM) {
        int t = eidx[E_NUM + e];
        int p = atomicAdd(&g_cursor[t], 1);
        g_edges[g_off[t] + p] = e;
    }
}

// ---------------- fused LN + SiLU epilogue + store ----------------
// Rows m0..m0+7 of the 128-row tile are each fully owned by one 16-lane
// half-warp (lanes with the same tid>>4), so row mean/var come from
// shfl_xor reductions with d in {1,2,4,8}.
__device__ __forceinline__ void ln_silu_store(
    float acc[8][8], int rowBase, int m0, int n0,
    const float* __restrict__ bias, const float* __restrict__ gam,
    const float* __restrict__ bet, float* __restrict__ out)
{
    float bv[8], gv[8], ev[8];
#pragma unroll
    for (int j = 0; j < 8; j++) {
        bv[j] = bias[n0 + j];
        gv[j] = gam[n0 + j];
        ev[j] = bet[n0 + j];
    }
#pragma unroll
    for (int i = 0; i < 8; i++) {
        float s = 0.f, s2 = 0.f;
#pragma unroll
        for (int j = 0; j < 8; j++) {
            float v = acc[i][j] + bv[j];
            acc[i][j] = v;
            s += v; s2 += v * v;
        }
#pragma unroll
        for (int d = 1; d < 16; d <<= 1) {
            s  += __shfl_xor_sync(0xffffffffu, s,  d);
            s2 += __shfl_xor_sync(0xffffffffu, s2, d);
        }
        float mean = s * (1.f / 128.f);
        float var  = s2 * (1.f / 128.f) - mean * mean;
        float rstd = rsqrtf(var + 1e-5f);
        float o[8];
#pragma unroll
        for (int j = 0; j < 8; j++) {
            float y = (acc[i][j] - mean) * rstd * gv[j] + ev[j];
            o[j] = y / (1.f + __expf(-y));
        }
        float* op = out + (size_t)(rowBase + m0 + i) * HID + n0;
        *(float4*)op       = make_float4(o[0], o[1], o[2], o[3]);
        *(float4*)(op + 4) = make_float4(o[4], o[5], o[6], o[7]);
    }
}

// ---------------- GEMM1: gathered [E,768] @ w1 -> LN -> SiLU -> g_h1 ----------------
__global__ __launch_bounds__(256) void k_gemm1(
    const int* __restrict__ an, const float* __restrict__ ed,
    const int* __restrict__ eidx, const float* __restrict__ srcT,
    const float* __restrict__ tgtT, const float* __restrict__ w1,
    const float* __restrict__ b1, const float* __restrict__ g1,
    const float* __restrict__ be1)
{
    __shared__ __align__(16) float As[16 * 132];
    __shared__ __align__(16) float Bs[16 * 128];
    const int tid = threadIdx.x;
    const int rowBase = blockIdx.x * 128;
    const int lm = tid >> 1;
    const int lk = (tid & 1) << 3;
    const int eRow = rowBase + lm;
    const float* edRow  = ed + (size_t)eRow * BASIS;
    const float* srcRow = srcT + (size_t)an[eidx[eRow]] * HID;
    const float* tgtRow = tgtT + (size_t)an[eidx[E_NUM + eRow]] * HID;
    const int kb = tid >> 4;
    const int nb = (tid & 15) << 3;
    const int m0 = (tid >> 4) << 3;
    const int n0 = (tid & 15) << 3;

    float acc[8][8];
#pragma unroll
    for (int i = 0; i < 8; i++)
#pragma unroll
        for (int j = 0; j < 8; j++) acc[i][j] = 0.f;

    for (int k0 = 0; k0 < DIN; k0 += 16) {
        int kg = k0 + lk;
        const float* ap;
        if (kg < BASIS)            ap = edRow + kg;
        else if (kg < BASIS + HID) ap = srcRow + (kg - BASIS);
        else                       ap = tgtRow + (kg - (BASIS + HID));
        float4 a0 = *(const float4*)ap;
        float4 a1 = *(const float4*)(ap + 4);
        As[(lk + 0) * 132 + lm] = a0.x;
        As[(lk + 1) * 132 + lm] = a0.y;
        As[(lk + 2) * 132 + lm] = a0.z;
        As[(lk + 3) * 132 + lm] = a0.w;
        As[(lk + 4) * 132 + lm] = a1.x;
        As[(lk + 5) * 132 + lm] = a1.y;
        As[(lk + 6) * 132 + lm] = a1.z;
        As[(lk + 7) * 132 + lm] = a1.w;

        const float* bp = w1 + (size_t)(k0 + kb) * HID + nb;
        *(float4*)&Bs[kb * 128 + nb]     = *(const float4*)bp;
        *(float4*)&Bs[kb * 128 + nb + 4] = *(const float4*)(bp + 4);
        __syncthreads();
#pragma unroll
        for (int kk = 0; kk < 16; kk++) {
            float4 ra0 = *(const float4*)&As[kk * 132 + m0];
            float4 ra1 = *(const float4*)&As[kk * 132 + m0 + 4];
            float4 rb0 = *(const float4*)&Bs[kk * 128 + n0];
            float4 rb1 = *(const float4*)&Bs[kk * 128 + n0 + 4];
            float a[8] = {ra0.x, ra0.y, ra0.z, ra0.w, ra1.x, ra1.y, ra1.z, ra1.w};
            float b[8] = {rb0.x, rb0.y, rb0.z, rb0.w, rb1.x, rb1.y, rb1.z, rb1.w};
#pragma unroll
            for (int i = 0; i < 8; i++)
#pragma unroll
                for (int j = 0; j < 8; j++)
                    acc[i][j] += a[i] * b[j];
        }
        __syncthreads();
    }
    ln_silu_store(acc, rowBase, m0, n0, b1, g1, be1, g_h1);
}

// ---------------- GEMM2: g_h1 @ w2 -> LN -> SiLU -> g_h2 ----------------
__global__ __launch_bounds__(256) void k_gemm2(
    const float* __restrict__ w2, const float* __restrict__ b2,
    const float* __restrict__ g2, const float* __restrict__ be2)
{
    __shared__ __align__(16) float As[16 * 132];
    __shared__ __align__(16) float Bs[16 * 128];
    const int tid = threadIdx.x;
    const int rowBase = blockIdx.x * 128;
    const int lm = tid >> 1;
    const int lk = (tid & 1) << 3;
    const int eRow = rowBase + lm;
    const int kb = tid >> 4;
    const int nb = (tid & 15) << 3;
    const int m0 = (tid >> 4) << 3;
    const int n0 = (tid & 15) << 3;

    float acc[8][8];
#pragma unroll
    for (int i = 0; i < 8; i++)
#pragma unroll
        for (int j = 0; j < 8; j++) acc[i][j] = 0.f;

    for (int k0 = 0; k0 < HID; k0 += 16) {
        const float* ap = g_h1 + (size_t)eRow * HID + k0 + lk;
        float4 a0 = *(const float4*)ap;
        float4 a1 = *(const float4*)(ap + 4);
        As[(lk + 0) * 132 + lm] = a0.x;
        As[(lk + 1) * 132 + lm] = a0.y;
        As[(lk + 2) * 132 + lm] = a0.z;
        As[(lk + 3) * 132 + lm] = a0.w;
        As[(lk + 4) * 132 + lm] = a1.x;
        As[(lk + 5) * 132 + lm] = a1.y;
        As[(lk + 6) * 132 + lm] = a1.z;
        As[(lk + 7) * 132 + lm] = a1.w;

        const float* bp = w2 + (size_t)(k0 + kb) * HID + nb;
        *(float4*)&Bs[kb * 128 + nb]     = *(const float4*)bp;
        *(float4*)&Bs[kb * 128 + nb + 4] = *(const float4*)(bp + 4);
        __syncthreads();
#pragma unroll
        for (int kk = 0; kk < 16; kk++) {
            float4 ra0 = *(const float4*)&As[kk * 132 + m0];
            float4 ra1 = *(const float4*)&As[kk * 132 + m0 + 4];
            float4 rb0 = *(const float4*)&Bs[kk * 128 + n0];
            float4 rb1 = *(const float4*)&Bs[kk * 128 + n0 + 4];
            float a[8] = {ra0.x, ra0.y, ra0.z, ra0.w, ra1.x, ra1.y, ra1.z, ra1.w};
            float b[8] = {rb0.x, rb0.y, rb0.z, rb0.w, rb1.x, rb1.y, rb1.z, rb1.w};
#pragma unroll
            for (int i = 0; i < 8; i++)
#pragma unroll
                for (int j = 0; j < 8; j++)
                    acc[i][j] += a[i] * b[j];
        }
        __syncthreads();
    }
    ln_silu_store(acc, rowBase, m0, n0, b2, g2, be2, g_h2);
}

// ---------------- GEMM3: g_h2 @ w3 + b3 -> g_x0 [E, 896] ----------------
__global__ __launch_bounds__(256) void k_gemm3(
    const float* __restrict__ w3, const float* __restrict__ b3)
{
    __shared__ __align__(16) float As[16 * 132];
    __shared__ __align__(16) float Bs[16 * 128];
    const int tid = threadIdx.x;
    const int rowBase = blockIdx.y * 128;
    const int nBase = blockIdx.x * 128;
    const int lm = tid >> 1;
    const int lk = (tid & 1) << 3;
    const int eRow = rowBase + lm;
    const int kb = tid >> 4;
    const int nb = (tid & 15) << 3;
    const int m0 = (tid >> 4) << 3;
    const int n0 = (tid & 15) << 3;

    float acc[8][8];
#pragma unroll
    for (int i = 0; i < 8; i++)
#pragma unroll
        for (int j = 0; j < 8; j++) acc[i][j] = 0.f;

    for (int k0 = 0; k0 < HID; k0 += 16) {
        const float* ap = g_h2 + (size_t)eRow * HID + k0 + lk;
        float4 a0 = *(const float4*)ap;
        float4 a1 = *(const float4*)(ap + 4);
        As[(lk + 0) * 132 + lm] = a0.x;
        As[(lk + 1) * 132 + lm] = a0.y;
        As[(lk + 2) * 132 + lm] = a0.z;
        As[(lk + 3) * 132 + lm] = a0.w;
        As[(lk + 4) * 132 + lm] = a1.x;
        As[(lk + 5) * 132 + lm] = a1.y;
        As[(lk + 6) * 132 + lm] = a1.z;
        As[(lk + 7) * 132 + lm] = a1.w;

        const float* bp = w3 + (size_t)(k0 + kb) * W3N + nBase + nb;
        *(float4*)&Bs[kb * 128 + nb]     = *(const float4*)bp;
        *(float4*)&Bs[kb * 128 + nb + 4] = *(const float4*)(bp + 4);
        __syncthreads();
#pragma unroll
        for (int kk = 0; kk < 16; kk++) {
            float4 ra0 = *(const float4*)&As[kk * 132 + m0];
            float4 ra1 = *(const float4*)&As[kk * 132 + m0 + 4];
            float4 rb0 = *(const float4*)&Bs[kk * 128 + n0];
            float4 rb1 = *(const float4*)&Bs[kk * 128 + n0 + 4];
            float a[8] = {ra0.x, ra0.y, ra0.z, ra0.w, ra1.x, ra1.y, ra1.z, ra1.w};
            float b[8] = {rb0.x, rb0.y, rb0.z, rb0.w, rb1.x, rb1.y, rb1.z, rb1.w};
#pragma unroll
            for (int i = 0; i < 8; i++)
#pragma unroll
                for (int j = 0; j < 8; j++)
                    acc[i][j] += a[i] * b[j];
        }
        __syncthreads();
    }
    // bias epilogue, store
    float bv[8];
#pragma unroll
    for (int j = 0; j < 8; j++) bv[j] = b3[nBase + n0 + j];
#pragma unroll
    for (int i = 0; i < 8; i++) {
        float* op = g_x0 + (size_t)(rowBase + m0 + i) * W3N + nBase + n0;
        *(float4*)op = make_float4(acc[i][0] + bv[0], acc[i][1] + bv[1],
                                   acc[i][2] + bv[2], acc[i][3] + bv[3]);
        *(float4*)(op + 4) = make_float4(acc[i][4] + bv[4], acc[i][5] + bv[5],
                                         acc[i][6] + bv[6], acc[i][7] + bv[7]);
    }
}

// ---------------- per-node rotate + reduce ----------------
// out[n,i,c] = (1/RESCALE) * sum_{e->n} sum_{m<7} wig[e,i,pos[m]] * x0[e,m,c]
__global__ __launch_bounds__(256) void k_node(
    const float* __restrict__ wig, float* __restrict__ out)
{
    __shared__ __align__(16) float Ws[WROW];      // 49 x 29
    __shared__ __align__(16) float Xs[M0C * CCH]; // 7 x 128
    const int tid = threadIdx.x;
    const int n = blockIdx.x;
    const int c4 = (tid & 31) << 2;   // column (x4)
    const int rg = tid >> 5;          // row group 0..7
    const int row0 = rg * 7;          // rows row0..row0+6 (guard <49)

    int pp[M0C];
#pragma unroll
    for (int m = 0; m < M0C; m++) pp[m] = g_pos[m];

    const int beg = g_off[n];
    const int end = g_off[n + 1];

    float acc[7][4];
#pragma unroll
    for (int r = 0; r < 7; r++)
#pragma unroll
        for (int j = 0; j < 4; j++) acc[r][j] = 0.f;

    for (int ii = beg; ii < end; ii++) {
        int e = g_edges[ii];
        // wigner tile: per-edge base (e*1421 floats) is not 16B-aligned -> scalar
        const float* wp = wig + (size_t)e * WROW;
        for (int i = tid; i < WROW; i += 256) Ws[i] = wp[i];
        // x0 tile: per-edge base (e*896 floats) IS 16B-aligned -> float4 staging
        const float4* xp4 = (const float4*)(g_x0 + (size_t)e * W3N);
        if (tid < (M0C * CCH) / 4) ((float4*)Xs)[tid] = xp4[tid];
        __syncthreads();

        float4 xv[M0C];
#pragma unroll
        for (int m = 0; m < M0C; m++)
            xv[m] = *(const float4*)&Xs[m * CCH + c4];

#pragma unroll
        for (int r = 0; r < 7; r++) {
            int row = row0 + r;
            if (row < NSPH) {
#pragma unroll
                for (int m = 0; m < M0C; m++) {
                    float w = Ws[row * NALL + pp[m]];
                    acc[r][0] += w * xv[m].x;
                    acc[r][1] += w * xv[m].y;
                    acc[r][2] += w * xv[m].z;
                    acc[r][3] += w * xv[m].w;
                }
            }
        }
        __syncthreads();
    }

    const float sc = (float)(1.0 / 23.395238876342773);
#pragma unroll
    for (int r = 0; r < 7; r++) {
        int row = row0 + r;
        if (row < NSPH) {
            float* op = out + (size_t)n * (NSPH * CCH) + row * CCH + c4;
            *(float4*)op = make_float4(acc[r][0] * sc, acc[r][1] * sc,
                                       acc[r][2] * sc, acc[r][3] * sc);
        }
    }
}

// ---------------- launch ----------------
extern "C" void kernel_launch(void* const* d_in, const int* in_sizes, int n_in,
                              void* d_out, int out_size)
{
    const int*   an   = (const int*)d_in[0];
    const float* ed   = (const float*)d_in[1];
    const int*   eidx = (const int*)d_in[2];
    const float* srcT = (const float*)d_in[3];
    const float* tgtT = (const float*)d_in[4];
    const float* w1   = (const float*)d_in[5];
    const float* b1   = (const float*)d_in[6];
    const float* g1   = (const float*)d_in[7];
    const float* be1  = (const float*)d_in[8];
    const float* w2   = (const float*)d_in[9];
    const float* b2   = (const float*)d_in[10];
    const float* g2   = (const float*)d_in[11];
    const float* be2  = (const float*)d_in[12];
    const float* w3   = (const float*)d_in[13];
    const float* b3   = (const float*)d_in[14];
    const float* tom  = (const float*)d_in[15];
    const float* wig  = (const float*)d_in[16];
    float* out = (float*)d_out;

    k_zero<<<(NODES + 255) / 256, 256>>>();
    k_hist<<<(E_NUM + 255) / 256, 256>>>(eidx);
    k_prep<<<1, 256>>>(tom);
    k_scatter<<<(E_NUM + 255) / 256, 256>>>(eidx);
    k_gemm1<<<E_NUM / 128, 256>>>(an, ed, eidx, srcT, tgtT, w1, b1, g1, be1);
    k_gemm2<<<E_NUM / 128, 256>>>(w2, b2, g2, be2);
    k_gemm3<<<dim3(W3N / 128, E_NUM / 128), 256>>>(w3, b3);
    k_node<<<NODES, 256>>>(wig, out);
}

// round 8
// speedup vs baseline: 1.1072x; 1.1072x over previous
#include <cuda_runtime.h>

#define E_NUM 32000
#define NODES 1600
#define CCH 128
#define M0C 7
#define NSPH 49
#define NALL 29
#define BASIS 512
#define HID 128
#define DIN 768
#define W3N 896
#define WROW (NSPH*NALL)   /* 1421 */
#define AS2S 264           /* As2 row stride in floats (132 dup pairs) */
#define NGATH (NSPH*M0C)   /* 343 */

typedef unsigned long long ull;

// ---------------- scratch (device globals: allocation-free) ----------------
__device__ float g_h1[(size_t)E_NUM * HID];
__device__ float g_h2[(size_t)E_NUM * HID];
__device__ float g_x0[(size_t)E_NUM * W3N];
__device__ int   g_count[NODES];
__device__ int   g_off[NODES + 1];
__device__ int   g_cursor[NODES];
__device__ int   g_edges[E_NUM];
__device__ int   g_pos[M0C];
__device__ int   g_wigidx[NGATH];   // precomputed r*NALL + pos[m]

// ---------------- f32x2 helpers ----------------
__device__ __forceinline__ ull dup2(float v) {
    ull r; asm("mov.b64 %0, {%1, %1};" : "=l"(r) : "f"(v)); return r;
}
__device__ __forceinline__ void unpk(ull p, float& lo, float& hi) {
    asm("mov.b64 {%0, %1}, %2;" : "=f"(lo), "=f"(hi) : "l"(p));
}
#define FMA2(acc, a, b) asm("fma.rn.f32x2 %0, %1, %2, %0;" : "+l"(acc) : "l"(a), "l"(b))

// ---------------- CSR build ----------------
__global__ void k_zero() {
    int i = blockIdx.x * 256 + threadIdx.x;
    if (i < NODES) { g_count[i] = 0; g_cursor[i] = 0; }
}

__global__ void k_hist(const int* __restrict__ eidx) {
    int e = blockIdx.x * 256 + threadIdx.x;
    if (e < E_NUM) atomicAdd(&g_count[eidx[E_NUM + e]], 1);
}

__global__ void k_prep(const float* __restrict__ tom) {
    __shared__ int csum[256];
    __shared__ int spos[M0C];
    int tid = threadIdx.x;
    if (tid < M0C) {
        int p = 0;
        for (int j = 0; j < NALL; j++)
            if (tom[tid * NALL + j] > 0.5f) p = j;
        g_pos[tid] = p;
        spos[tid] = p;
    }
    __syncthreads();
    // precomputed gather index table for k_node
    for (int i = tid; i < NGATH; i += 256) {
        int r = i / M0C;
        int m = i - r * M0C;
        g_wigidx[i] = r * NALL + spos[m];
    }
    int base = tid * 7;
    int s = 0;
    for (int i = 0; i < 7; i++) {
        int idx = base + i;
        if (idx < NODES) s += g_count[idx];
    }
    csum[tid] = s;
    __syncthreads();
    if (tid == 0) {
        int run = 0;
        for (int i = 0; i < 256; i++) { int t = csum[i]; csum[i] = run; run += t; }
        g_off[NODES] = run;
    }
    __syncthreads();
    int run = csum[tid];
    for (int i = 0; i < 7; i++) {
        int idx = base + i;
        if (idx < NODES) { g_off[idx] = run; run += g_count[idx]; }
    }
}

__global__ void k_scatter(const int* __restrict__ eidx) {
    int e = blockIdx.x * 256 + threadIdx.x;
    if (e < E_NUM) {
        int t = eidx[E_NUM + e];
        int p = atomicAdd(&g_cursor[t], 1);
        g_edges[g_off[t] + p] = e;
    }
}

// ---------------- fused LN + SiLU epilogue + store ----------------
__device__ __forceinline__ void ln_silu_store(
    float acc[8][8], int rowBase, int m0, int n0,
    const float* __restrict__ bias, const float* __restrict__ gam,
    const float* __restrict__ bet, float* __restrict__ out)
{
    float bv[8], gv[8], ev[8];
#pragma unroll
    for (int j = 0; j < 8; j++) {
        bv[j] = bias[n0 + j];
        gv[j] = gam[n0 + j];
        ev[j] = bet[n0 + j];
    }
#pragma unroll
    for (int i = 0; i < 8; i++) {
        float s = 0.f, s2 = 0.f;
#pragma unroll
        for (int j = 0; j < 8; j++) {
            float v = acc[i][j] + bv[j];
            acc[i][j] = v;
            s += v; s2 += v * v;
        }
#pragma unroll
        for (int d = 1; d < 16; d <<= 1) {
            s  += __shfl_xor_sync(0xffffffffu, s,  d);
            s2 += __shfl_xor_sync(0xffffffffu, s2, d);
        }
        float mean = s * (1.f / 128.f);
        float var  = s2 * (1.f / 128.f) - mean * mean;
        float rstd = rsqrtf(var + 1e-5f);
        float o[8];
#pragma unroll
        for (int j = 0; j < 8; j++) {
            float y = (acc[i][j] - mean) * rstd * gv[j] + ev[j];
            o[j] = y / (1.f + __expf(-y));
        }
        float* op = out + (size_t)(rowBase + m0 + i) * HID + n0;
        *(float4*)op       = make_float4(o[0], o[1], o[2], o[3]);
        *(float4*)(op + 4) = make_float4(o[4], o[5], o[6], o[7]);
    }
}

// Store one thread's 8 k-slice values into the duplicated A tile.
__device__ __forceinline__ void stage_a_dup(float* As2, int lk, int lm,
                                            float4 a0, float4 a1)
{
    *(ull*)&As2[(lk + 0) * AS2S + 2 * lm] = dup2(a0.x);
    *(ull*)&As2[(lk + 1) * AS2S + 2 * lm] = dup2(a0.y);
    *(ull*)&As2[(lk + 2) * AS2S + 2 * lm] = dup2(a0.z);
    *(ull*)&As2[(lk + 3) * AS2S + 2 * lm] = dup2(a0.w);
    *(ull*)&As2[(lk + 4) * AS2S + 2 * lm] = dup2(a1.x);
    *(ull*)&As2[(lk + 5) * AS2S + 2 * lm] = dup2(a1.y);
    *(ull*)&As2[(lk + 6) * AS2S + 2 * lm] = dup2(a1.z);
    *(ull*)&As2[(lk + 7) * AS2S + 2 * lm] = dup2(a1.w);
}

// f32x2 mainloop step: 8 dup A-pairs x 4 B-pairs -> 32 FFMA2
__device__ __forceinline__ void mma_step(const float* As2, const float* Bs,
                                         int kk, int m0, int n0, ull acc2[8][4])
{
    ulonglong2 ra0 = *(const ulonglong2*)&As2[kk * AS2S + 2 * m0];
    ulonglong2 ra1 = *(const ulonglong2*)&As2[kk * AS2S + 2 * m0 + 4];
    ulonglong2 ra2 = *(const ulonglong2*)&As2[kk * AS2S + 2 * m0 + 8];
    ulonglong2 ra3 = *(const ulonglong2*)&As2[kk * AS2S + 2 * m0 + 12];
    ulonglong2 rb0 = *(const ulonglong2*)&Bs[kk * 128 + n0];
    ulonglong2 rb1 = *(const ulonglong2*)&Bs[kk * 128 + n0 + 4];
    ull a2[8] = {ra0.x, ra0.y, ra1.x, ra1.y, ra2.x, ra2.y, ra3.x, ra3.y};
    ull b2[4] = {rb0.x, rb0.y, rb1.x, rb1.y};
#pragma unroll
    for (int i = 0; i < 8; i++)
#pragma unroll
        for (int j = 0; j < 4; j++)
            FMA2(acc2[i][j], a2[i], b2[j]);
}

__device__ __forceinline__ void unpack_acc(ull acc2[8][4], float acc[8][8])
{
#pragma unroll
    for (int i = 0; i < 8; i++)
#pragma unroll
        for (int j = 0; j < 4; j++)
            unpk(acc2[i][j], acc[i][2 * j], acc[i][2 * j + 1]);
}

// ---------------- GEMM1: gathered [E,768] @ w1 -> LN -> SiLU -> g_h1 ----------------
__global__ __launch_bounds__(256) void k_gemm1(
    const int* __restrict__ an, const float* __restrict__ ed,
    const int* __restrict__ eidx, const float* __restrict__ srcT,
    const float* __restrict__ tgtT, const float* __restrict__ w1,
    const float* __restrict__ b1, const float* __restrict__ g1,
    const float* __restrict__ be1)
{
    __shared__ __align__(16) float As2[16 * AS2S];
    __shared__ __align__(16) float Bs[16 * 128];
    const int tid = threadIdx.x;
    const int rowBase = blockIdx.x * 128;
    const int lm = tid >> 1;
    const int lk = (tid & 1) << 3;
    const int eRow = rowBase + lm;
    const float* edRow  = ed + (size_t)eRow * BASIS;
    const float* srcRow = srcT + (size_t)an[eidx[eRow]] * HID;
    const float* tgtRow = tgtT + (size_t)an[eidx[E_NUM + eRow]] * HID;
    const int kb = tid >> 4;
    const int nb = (tid & 15) << 3;
    const int m0 = (tid >> 4) << 3;
    const int n0 = (tid & 15) << 3;

    ull acc2[8][4];
#pragma unroll
    for (int i = 0; i < 8; i++)
#pragma unroll
        for (int j = 0; j < 4; j++) acc2[i][j] = 0ull;

    for (int k0 = 0; k0 < DIN; k0 += 16) {
        int kg = k0 + lk;
        const float* ap;
        if (kg < BASIS)            ap = edRow + kg;
        else if (kg < BASIS + HID) ap = srcRow + (kg - BASIS);
        else                       ap = tgtRow + (kg - (BASIS + HID));
        float4 a0 = *(const float4*)ap;
        float4 a1 = *(const float4*)(ap + 4);
        stage_a_dup(As2, lk, lm, a0, a1);

        const float* bp = w1 + (size_t)(k0 + kb) * HID + nb;
        *(float4*)&Bs[kb * 128 + nb]     = *(const float4*)bp;
        *(float4*)&Bs[kb * 128 + nb + 4] = *(const float4*)(bp + 4);
        __syncthreads();
#pragma unroll
        for (int kk = 0; kk < 16; kk++)
            mma_step(As2, Bs, kk, m0, n0, acc2);
        __syncthreads();
    }
    float acc[8][8];
    unpack_acc(acc2, acc);
    ln_silu_store(acc, rowBase, m0, n0, b1, g1, be1, g_h1);
}

// ---------------- GEMM2: g_h1 @ w2 -> LN -> SiLU -> g_h2 ----------------
__global__ __launch_bounds__(256) void k_gemm2(
    const float* __restrict__ w2, const float* __restrict__ b2,
    const float* __restrict__ g2, const float* __restrict__ be2)
{
    __shared__ __align__(16) float As2[16 * AS2S];
    __shared__ __align__(16) float Bs[16 * 128];
    const int tid = threadIdx.x;
    const int rowBase = blockIdx.x * 128;
    const int lm = tid >> 1;
    const int lk = (tid & 1) << 3;
    const int eRow = rowBase + lm;
    const int kb = tid >> 4;
    const int nb = (tid & 15) << 3;
    const int m0 = (tid >> 4) << 3;
    const int n0 = (tid & 15) << 3;

    ull acc2[8][4];
#pragma unroll
    for (int i = 0; i < 8; i++)
#pragma unroll
        for (int j = 0; j < 4; j++) acc2[i][j] = 0ull;

    for (int k0 = 0; k0 < HID; k0 += 16) {
        const float* ap = g_h1 + (size_t)eRow * HID + k0 + lk;
        float4 a0 = *(const float4*)ap;
        float4 a1 = *(const float4*)(ap + 4);
        stage_a_dup(As2, lk, lm, a0, a1);

        const float* bp = w2 + (size_t)(k0 + kb) * HID + nb;
        *(float4*)&Bs[kb * 128 + nb]     = *(const float4*)bp;
        *(float4*)&Bs[kb * 128 + nb + 4] = *(const float4*)(bp + 4);
        __syncthreads();
#pragma unroll
        for (int kk = 0; kk < 16; kk++)
            mma_step(As2, Bs, kk, m0, n0, acc2);
        __syncthreads();
    }
    float acc[8][8];
    unpack_acc(acc2, acc);
    ln_silu_store(acc, rowBase, m0, n0, b2, g2, be2, g_h2);
}

// ---------------- GEMM3: g_h2 @ w3 + b3 -> g_x0 [E, 896] ----------------
__global__ __launch_bounds__(256) void k_gemm3(
    const float* __restrict__ w3, const float* __restrict__ b3)
{
    __shared__ __align__(16) float As2[16 * AS2S];
    __shared__ __align__(16) float Bs[16 * 128];
    const int tid = threadIdx.x;
    const int rowBase = blockIdx.y * 128;
    const int nBase = blockIdx.x * 128;
    const int lm = tid >> 1;
    const int lk = (tid & 1) << 3;
    const int eRow = rowBase + lm;
    const int kb = tid >> 4;
    const int nb = (tid & 15) << 3;
    const int m0 = (tid >> 4) << 3;
    const int n0 = (tid & 15) << 3;

    ull acc2[8][4];
#pragma unroll
    for (int i = 0; i < 8; i++)
#pragma unroll
        for (int j = 0; j < 4; j++) acc2[i][j] = 0ull;

    for (int k0 = 0; k0 < HID; k0 += 16) {
        const float* ap = g_h2 + (size_t)eRow * HID + k0 + lk;
        float4 a0 = *(const float4*)ap;
        float4 a1 = *(const float4*)(ap + 4);
        stage_a_dup(As2, lk, lm, a0, a1);

        const float* bp = w3 + (size_t)(k0 + kb) * W3N + nBase + nb;
        *(float4*)&Bs[kb * 128 + nb]     = *(const float4*)bp;
        *(float4*)&Bs[kb * 128 + nb + 4] = *(const float4*)(bp + 4);
        __syncthreads();
#pragma unroll
        for (int kk = 0; kk < 16; kk++)
            mma_step(As2, Bs, kk, m0, n0, acc2);
        __syncthreads();
    }
    float acc[8][8];
    unpack_acc(acc2, acc);
    float bv[8];
#pragma unroll
    for (int j = 0; j < 8; j++) bv[j] = b3[nBase + n0 + j];
#pragma unroll
    for (int i = 0; i < 8; i++) {
        float* op = g_x0 + (size_t)(rowBase + m0 + i) * W3N + nBase + n0;
        *(float4*)op = make_float4(acc[i][0] + bv[0], acc[i][1] + bv[1],
                                   acc[i][2] + bv[2], acc[i][3] + bv[3]);
        *(float4*)(op + 4) = make_float4(acc[i][4] + bv[4], acc[i][5] + bv[5],
                                         acc[i][6] + bv[6], acc[i][7] + bv[7]);
    }
}

// ---------------- per-node rotate + reduce (f32x2, gathered dup weights) ----
// out[n,i,c] = (1/RESCALE) * sum_{e->n} sum_{m<7} wig[e,i,pos[m]] * x0[e,m,c]
__global__ __launch_bounds__(256) void k_node(
    const float* __restrict__ wig, float* __restrict__ out)
{
    __shared__ __align__(16) ull   Wg2[NGATH];        // 343 dup pairs (w,w)
    __shared__ __align__(16) float Xs[M0C * CCH];     // 7 x 128
    const int tid = threadIdx.x;
    const int n = blockIdx.x;
    const int c4 = (tid & 31) << 2;   // column (x4)
    const int rg = tid >> 5;          // row group 0..7
    const int row0 = rg * 7;          // rows row0..row0+6 (guard <49)

    const int beg = g_off[n];
    const int end = g_off[n + 1];

    // each thread covers gather slots tid and tid+256 (343 total)
    const int gi0 = tid;
    const int gi1 = tid + 256;
    const int widx0 = g_wigidx[gi0 < NGATH ? gi0 : 0];
    const int widx1 = (gi1 < NGATH) ? g_wigidx[gi1] : 0;

    ull acc2[7][2];
#pragma unroll
    for (int r = 0; r < 7; r++) { acc2[r][0] = 0ull; acc2[r][1] = 0ull; }

    for (int ii = beg; ii < end; ii++) {
        int e = g_edges[ii];
        const float* wp = wig + (size_t)e * WROW;
        if (gi0 < NGATH) Wg2[gi0] = dup2(wp[widx0]);
        if (gi1 < NGATH) Wg2[gi1] = dup2(wp[widx1]);
        // x0 tile: per-edge base (e*896 floats) is 16B-aligned -> float4
        const float4* xp4 = (const float4*)(g_x0 + (size_t)e * W3N);
        if (tid < (M0C * CCH) / 4) ((float4*)Xs)[tid] = xp4[tid];
        __syncthreads();

        ull xa[M0C], xb[M0C];
#pragma unroll
        for (int m = 0; m < M0C; m++) {
            ulonglong2 xp = *(const ulonglong2*)&Xs[m * CCH + c4];
            xa[m] = xp.x; xb[m] = xp.y;
        }

#pragma unroll
        for (int r = 0; r < 7; r++) {
            int row = row0 + r;
            if (row < NSPH) {
#pragma unroll
                for (int m = 0; m < M0C; m++) {
                    ull w2 = Wg2[row * M0C + m];
                    FMA2(acc2[r][0], w2, xa[m]);
                    FMA2(acc2[r][1], w2, xb[m]);
                }
            }
        }
        __syncthreads();
    }

    const float sc = (float)(1.0 / 23.395238876342773);
#pragma unroll
    for (int r = 0; r < 7; r++) {
        int row = row0 + r;
        if (row < NSPH) {
            float v0, v1, v2, v3;
            unpk(acc2[r][0], v0, v1);
            unpk(acc2[r][1], v2, v3);
            float* op = out + (size_t)n * (NSPH * CCH) + row * CCH + c4;
            *(float4*)op = make_float4(v0 * sc, v1 * sc, v2 * sc, v3 * sc);
        }
    }
}

// ---------------- launch ----------------
extern "C" void kernel_launch(void* const* d_in, const int* in_sizes, int n_in,
                              void* d_out, int out_size)
{
    const int*   an   = (const int*)d_in[0];
    const float* ed   = (const float*)d_in[1];
    const int*   eidx = (const int*)d_in[2];
    const float* srcT = (const float*)d_in[3];
    const float* tgtT = (const float*)d_in[4];
    const float* w1   = (const float*)d_in[5];
    const float* b1   = (const float*)d_in[6];
    const float* g1   = (const float*)d_in[7];
    const float* be1  = (const float*)d_in[8];
    const float* w2   = (const float*)d_in[9];
    const float* b2   = (const float*)d_in[10];
    const float* g2   = (const float*)d_in[11];
    const float* be2  = (const float*)d_in[12];
    const float* w3   = (const float*)d_in[13];
    const float* b3   = (const float*)d_in[14];
    const float* tom  = (const float*)d_in[15];
    const float* wig  = (const float*)d_in[16];
    float* out = (float*)d_out;

    k_zero<<<(NODES + 255) / 256, 256>>>();
    k_hist<<<(E_NUM + 255) / 256, 256>>>(eidx);
    k_prep<<<1, 256>>>(tom);
    k_scatter<<<(E_NUM + 255) / 256, 256>>>(eidx);
    k_gemm1<<<E_NUM / 128, 256>>>(an, ed, eidx, srcT, tgtT, w1, b1, g1, be1);
    k_gemm2<<<E_NUM / 128, 256>>>(w2, b2, g2, be2);
    k_gemm3<<<dim3(W3N / 128, E_NUM / 128), 256>>>(w3, b3);
    k_node<<<NODES, 256>>>(wig, out);
}

// round 11
// speedup vs baseline: 1.8071x; 1.6322x over previous
#include <cuda_runtime.h>

#define E_NUM 32000
#define NODES 1600
#define CCH 128
#define M0C 7
#define NSPH 49
#define NALL 29
#define BASIS 512
#define HID 128
#define DIN 768
#define W3N 896
#define WROW (NSPH*NALL)   /* 1421 */
#define NGATH (NSPH*M0C)   /* 343 */

#define AST 40    /* A smem row stride in bf16 elems (padded, conflict-free) */
#define BST 136   /* B smem row stride in bf16 elems (padded, conflict-free) */

typedef unsigned long long ull;
typedef unsigned int u32;
typedef unsigned short u16;

// ---------------- scratch (device globals: allocation-free) ----------------
__device__ float g_h1[(size_t)E_NUM * HID];
__device__ float g_h2[(size_t)E_NUM * HID];
__device__ float g_x0[(size_t)E_NUM * W3N];
__device__ int   g_count[NODES];
__device__ int   g_off[NODES + 1];
__device__ int   g_cursor[NODES];
__device__ int   g_edges[E_NUM];
__device__ int   g_wigidx[NGATH];

// ---------------- helpers ----------------
__device__ __forceinline__ u32 smem_u32(const void* p) {
    u32 a;
    asm("{ .reg .u64 t; cvta.to.shared.u64 t, %1; cvt.u32.u64 %0, t; }"
        : "=r"(a) : "l"(p));
    return a;
}
__device__ __forceinline__ ull dup2(float v) {
    ull r; asm("mov.b64 %0, {%1, %1};" : "=l"(r) : "f"(v)); return r;
}
__device__ __forceinline__ void unpk(ull p, float& lo, float& hi) {
    asm("mov.b64 {%0, %1}, %2;" : "=f"(lo), "=f"(hi) : "l"(p));
}
#define FMA2(acc, a, b) asm("fma.rn.f32x2 %0, %1, %2, %0;" : "+l"(acc) : "l"(a), "l"(b))

// split pair (a0,a1): hi = packed bf16x2 (a0 in low half), lo = packed residual
__device__ __forceinline__ void split2(float a0, float a1, u32& hi, u32& lo) {
    u32 h;
    asm("cvt.rn.satfinite.bf16x2.f32 %0, %1, %2;" : "=r"(h) : "f"(a1), "f"(a0));
    float hf0 = __uint_as_float(h << 16);
    float hf1 = __uint_as_float(h & 0xffff0000u);
    float l0 = a0 - hf0, l1 = a1 - hf1;
    asm("cvt.rn.satfinite.bf16x2.f32 %0, %1, %2;" : "=r"(lo) : "f"(l1), "f"(l0));
    hi = h;
}

#define LDSM4(r0,r1,r2,r3,a) \
    asm volatile("ldmatrix.sync.aligned.m8n8.x4.shared.b16 {%0,%1,%2,%3}, [%4];" \
                 : "=r"(r0), "=r"(r1), "=r"(r2), "=r"(r3) : "r"(a))
#define LDSM4T(r0,r1,r2,r3,a) \
    asm volatile("ldmatrix.sync.aligned.m8n8.x4.trans.shared.b16 {%0,%1,%2,%3}, [%4];" \
                 : "=r"(r0), "=r"(r1), "=r"(r2), "=r"(r3) : "r"(a))
#define MMA_BF16(d, a0,a1,a2,a3, b0,b1) \
    asm volatile("mma.sync.aligned.m16n8k16.row.col.f32.bf16.bf16.f32 " \
                 "{%0,%1,%2,%3}, {%4,%5,%6,%7}, {%8,%9}, {%0,%1,%2,%3};" \
                 : "+f"((d)[0]), "+f"((d)[1]), "+f"((d)[2]), "+f"((d)[3]) \
                 : "r"(a0), "r"(a1), "r"(a2), "r"(a3), "r"(b0), "r"(b1))

// ---------------- CSR build ----------------
__global__ void k_zero() {
    int i = blockIdx.x * 256 + threadIdx.x;
    if (i < NODES) { g_count[i] = 0; g_cursor[i] = 0; }
}
__global__ void k_hist(const int* __restrict__ eidx) {
    int e = blockIdx.x * 256 + threadIdx.x;
    if (e < E_NUM) atomicAdd(&g_count[eidx[E_NUM + e]], 1);
}
__global__ void k_prep(const float* __restrict__ tom) {
    __shared__ int csum[256];
    __shared__ int spos[M0C];
    int tid = threadIdx.x;
    if (tid < M0C) {
        int p = 0;
        for (int j = 0; j < NALL; j++)
            if (tom[tid * NALL + j] > 0.5f) p = j;
        spos[tid] = p;
    }
    __syncthreads();
    for (int i = tid; i < NGATH; i += 256) {
        int r = i / M0C;
        int m = i - r * M0C;
        g_wigidx[i] = r * NALL + spos[m];
    }
    int base = tid * 7;
    int s = 0;
    for (int i = 0; i < 7; i++) {
        int idx = base + i;
        if (idx < NODES) s += g_count[idx];
    }
    csum[tid] = s;
    __syncthreads();
    if (tid == 0) {
        int run = 0;
        for (int i = 0; i < 256; i++) { int t = csum[i]; csum[i] = run; run += t; }
        g_off[NODES] = run;
    }
    __syncthreads();
    int run = csum[tid];
    for (int i = 0; i < 7; i++) {
        int idx = base + i;
        if (idx < NODES) { g_off[idx] = run; run += g_count[idx]; }
    }
}
__global__ void k_scatter(const int* __restrict__ eidx) {
    int e = blockIdx.x * 256 + threadIdx.x;
    if (e < E_NUM) {
        int t = eidx[E_NUM + e];
        int p = atomicAdd(&g_cursor[t], 1);
        g_edges[g_off[t] + p] = e;
    }
}

// ---------------- shared MMA machinery ----------------
// one BK=32 iteration of 3-term split mma over the staged smem tiles
__device__ __forceinline__ void compute_iter(u32 ahB, u32 alB, u32 bhB, u32 blB,
                                             float acc[2][8][4])
{
#pragma unroll
    for (int ks = 0; ks < 2; ks++) {
        u32 ah[2][4], al[2][4];
#pragma unroll
        for (int mt = 0; mt < 2; mt++) {
            LDSM4(ah[mt][0], ah[mt][1], ah[mt][2], ah[mt][3],
                  ahB + mt * (16 * AST * 2) + ks * 32);
            LDSM4(al[mt][0], al[mt][1], al[mt][2], al[mt][3],
                  alB + mt * (16 * AST * 2) + ks * 32);
        }
        u32 bh[4][4], bl[4][4];
#pragma unroll
        for (int p = 0; p < 4; p++) {
            LDSM4T(bh[p][0], bh[p][1], bh[p][2], bh[p][3],
                   bhB + ks * (16 * BST * 2) + p * 32);
            LDSM4T(bl[p][0], bl[p][1], bl[p][2], bl[p][3],
                   blB + ks * (16 * BST * 2) + p * 32);
        }
#pragma unroll
        for (int mt = 0; mt < 2; mt++)
#pragma unroll
            for (int p = 0; p < 4; p++)
#pragma unroll
                for (int h = 0; h < 2; h++) {
                    int nt = p * 2 + h;
                    MMA_BF16(acc[mt][nt], ah[mt][0], ah[mt][1], ah[mt][2], ah[mt][3],
                             bh[p][h * 2], bh[p][h * 2 + 1]);
                    MMA_BF16(acc[mt][nt], ah[mt][0], ah[mt][1], ah[mt][2], ah[mt][3],
                             bl[p][h * 2], bl[p][h * 2 + 1]);
                    MMA_BF16(acc[mt][nt], al[mt][0], al[mt][1], al[mt][2], al[mt][3],
                             bh[p][h * 2], bh[p][h * 2 + 1]);
                }
    }
}

__device__ __forceinline__ void stage_a16(u16* Ahs, u16* Als, int r, int kh,
                                          const float4* ap)
{
#pragma unroll
    for (int j = 0; j < 4; j++) {
        float4 f = ap[j];
        u32 h0, l0, h1, l1;
        split2(f.x, f.y, h0, l0);
        split2(f.z, f.w, h1, l1);
        int off = r * AST + kh + j * 4;
        *(u32*)&Ahs[off] = h0; *(u32*)&Ahs[off + 2] = h1;
        *(u32*)&Als[off] = l0; *(u32*)&Als[off + 2] = l1;
    }
}
__device__ __forceinline__ void stage_b16(u16* Bhs, u16* Bls, int bk, int bc,
                                          const float4* bp)
{
#pragma unroll
    for (int j = 0; j < 4; j++) {
        float4 f = bp[j];
        u32 h0, l0, h1, l1;
        split2(f.x, f.y, h0, l0);
        split2(f.z, f.w, h1, l1);
        int off = bk * BST + bc + j * 4;
        *(u32*)&Bhs[off] = h0; *(u32*)&Bhs[off + 2] = h1;
        *(u32*)&Bls[off] = l0; *(u32*)&Bls[off + 2] = l1;
    }
}

// fused bias + LN + SiLU epilogue with cross-warp row reduction, fp32 store
__device__ __forceinline__ void ln_epi_mma(
    float acc[2][8][4], int rowBase, int wr, int wc, int lane,
    const float* __restrict__ bias, const float* __restrict__ gam,
    const float* __restrict__ bet, float* __restrict__ out,
    float* redS, float* redQ)
{
    int gid = lane >> 2, q = lane & 3;
#pragma unroll
    for (int mt = 0; mt < 2; mt++)
#pragma unroll
        for (int sub = 0; sub < 2; sub++) {
            int rl = wr * 32 + mt * 16 + sub * 8 + gid;
            float s = 0.f, s2 = 0.f;
#pragma unroll
            for (int nt = 0; nt < 8; nt++)
#pragma unroll
                for (int e = 0; e < 2; e++) {
                    int col = wc * 64 + nt * 8 + q * 2 + e;
                    float v = acc[mt][nt][sub * 2 + e] + bias[col];
                    acc[mt][nt][sub * 2 + e] = v;
                    s += v; s2 += v * v;
                }
            s  += __shfl_xor_sync(0xffffffffu, s, 1);
            s  += __shfl_xor_sync(0xffffffffu, s, 2);
            s2 += __shfl_xor_sync(0xffffffffu, s2, 1);
            s2 += __shfl_xor_sync(0xffffffffu, s2, 2);
            if (q == 0) { redS[rl * 2 + wc] = s; redQ[rl * 2 + wc] = s2; }
        }
    __syncthreads();
#pragma unroll
    for (int mt = 0; mt < 2; mt++)
#pragma unroll
        for (int sub = 0; sub < 2; sub++) {
            int rl = wr * 32 + mt * 16 + sub * 8 + gid;
            float st = redS[rl * 2] + redS[rl * 2 + 1];
            float st2 = redQ[rl * 2] + redQ[rl * 2 + 1];
            float mean = st * (1.f / 128.f);
            float var = st2 * (1.f / 128.f) - mean * mean;
            float rstd = rsqrtf(var + 1e-5f);
            float* op = out + (size_t)(rowBase + rl) * HID;
#pragma unroll
            for (int nt = 0; nt < 8; nt++) {
                int col = wc * 64 + nt * 8 + q * 2;
                float y0 = (acc[mt][nt][sub * 2] - mean) * rstd * gam[col] + bet[col];
                float y1 = (acc[mt][nt][sub * 2 + 1] - mean) * rstd * gam[col + 1] + bet[col + 1];
                float o0 = y0 / (1.f + __expf(-y0));
                float o1 = y1 / (1.f + __expf(-y1));
                *(float2*)(op + col) = make_float2(o0, o1);
            }
        }
}

// ---------------- GEMM1: gathered [E,768] @ w1 -> LN/SiLU -> g_h1 ----------
__global__ __launch_bounds__(256) void k_mgemm1(
    const int* __restrict__ an, const float* __restrict__ ed,
    const int* __restrict__ eidx, const float* __restrict__ srcT,
    const float* __restrict__ tgtT, const float* __restrict__ w1,
    const float* __restrict__ b1, const float* __restrict__ g1,
    const float* __restrict__ be1)
{
    __shared__ __align__(16) u16 Ahs[128 * AST], Als[128 * AST];
    __shared__ __align__(16) u16 Bhs[32 * BST], Bls[32 * BST];
    __shared__ float redS[128 * 2], redQ[128 * 2];
    const int tid = threadIdx.x, lane = tid & 31, wid = tid >> 5;
    const int wr = wid >> 1, wc = wid & 1;
    const int rowBase = blockIdx.x * 128;

    const int r = tid >> 1, kh = (tid & 1) * 16;
    const int eRow = rowBase + r;
    const float* edRow = ed + (size_t)eRow * BASIS;
    const float* srcRow = srcT + (size_t)an[eidx[eRow]] * HID;
    const float* tgtRow = tgtT + (size_t)an[eidx[E_NUM + eRow]] * HID;
    const int bk = tid >> 3, bc = (tid & 7) * 16;

    const int ln15 = lane & 15, hb = (lane >> 4) * 16;
    u32 ahB = smem_u32(Ahs) + 2 * ((wr * 32 + ln15) * AST) + hb;
    u32 alB = smem_u32(Als) + 2 * ((wr * 32 + ln15) * AST) + hb;
    u32 bhB = smem_u32(Bhs) + 2 * (ln15 * BST + wc * 64) + hb;
    u32 blB = smem_u32(Bls) + 2 * (ln15 * BST + wc * 64) + hb;

    float acc[2][8][4];
#pragma unroll
    for (int i = 0; i < 2; i++)
#pragma unroll
        for (int j = 0; j < 8; j++)
#pragma unroll
            for (int k = 0; k < 4; k++) acc[i][j][k] = 0.f;

    for (int k0 = 0; k0 < DIN; k0 += 32) {
        int kg = k0 + kh;
        const float* ap = (kg < BASIS) ? edRow + kg
                        : (kg < BASIS + HID) ? srcRow + (kg - BASIS)
                        : tgtRow + (kg - BASIS - HID);
        float4 af[4], bf[4];
        const float4* ap4 = (const float4*)ap;
        const float4* bp4 = (const float4*)(w1 + (size_t)(k0 + bk) * HID + bc);
#pragma unroll
        for (int j = 0; j < 4; j++) { af[j] = ap4[j]; bf[j] = bp4[j]; }
        __syncthreads();
        stage_a16(Ahs, Als, r, kh, af);
        stage_b16(Bhs, Bls, bk, bc, bf);
        __syncthreads();
        compute_iter(ahB, alB, bhB, blB, acc);
    }
    ln_epi_mma(acc, rowBase, wr, wc, lane, b1, g1, be1, g_h1, redS, redQ);
}

// ---------------- GEMM2: g_h1 @ w2 -> LN/SiLU -> g_h2 ----------------------
__global__ __launch_bounds__(256) void k_mgemm2(
    const float* __restrict__ w2, const float* __restrict__ b2,
    const float* __restrict__ g2, const float* __restrict__ be2)
{
    __shared__ __align__(16) u16 Ahs[128 * AST], Als[128 * AST];
    __shared__ __align__(16) u16 Bhs[32 * BST], Bls[32 * BST];
    __shared__ float redS[128 * 2], redQ[128 * 2];
    const int tid = threadIdx.x, lane = tid & 31, wid = tid >> 5;
    const int wr = wid >> 1, wc = wid & 1;
    const int rowBase = blockIdx.x * 128;
    const int r = tid >> 1, kh = (tid & 1) * 16;
    const int eRow = rowBase + r;
    const int bk = tid >> 3, bc = (tid & 7) * 16;

    const int ln15 = lane & 15, hb = (lane >> 4) * 16;
    u32 ahB = smem_u32(Ahs) + 2 * ((wr * 32 + ln15) * AST) + hb;
    u32 alB = smem_u32(Als) + 2 * ((wr * 32 + ln15) * AST) + hb;
    u32 bhB = smem_u32(Bhs) + 2 * (ln15 * BST + wc * 64) + hb;
    u32 blB = smem_u32(Bls) + 2 * (ln15 * BST + wc * 64) + hb;

    float acc[2][8][4];
#pragma unroll
    for (int i = 0; i < 2; i++)
#pragma unroll
        for (int j = 0; j < 8; j++)
#pragma unroll
            for (int k = 0; k < 4; k++) acc[i][j][k] = 0.f;

    for (int k0 = 0; k0 < HID; k0 += 32) {
        float4 af[4], bf[4];
        const float4* ap4 = (const float4*)(g_h1 + (size_t)eRow * HID + k0 + kh);
        const float4* bp4 = (const float4*)(w2 + (size_t)(k0 + bk) * HID + bc);
#pragma unroll
        for (int j = 0; j < 4; j++) { af[j] = ap4[j]; bf[j] = bp4[j]; }
        __syncthreads();
        stage_a16(Ahs, Als, r, kh, af);
        stage_b16(Bhs, Bls, bk, bc, bf);
        __syncthreads();
        compute_iter(ahB, alB, bhB, blB, acc);
    }
    ln_epi_mma(acc, rowBase, wr, wc, lane, b2, g2, be2, g_h2, redS, redQ);
}

// ---------------- GEMM3: g_h2 @ w3 + b3 -> g_x0 [E,896] --------------------
__global__ __launch_bounds__(256) void k_mgemm3(
    const float* __restrict__ w3, const float* __restrict__ b3)
{
    __shared__ __align__(16) u16 Ahs[128 * AST], Als[128 * AST];
    __shared__ __align__(16) u16 Bhs[32 * BST], Bls[32 * BST];
    const int tid = threadIdx.x, lane = tid & 31, wid = tid >> 5;
    const int wr = wid >> 1, wc = wid & 1;
    const int rowBase = blockIdx.y * 128;
    const int nBase = blockIdx.x * 128;
    const int r = tid >> 1, kh = (tid & 1) * 16;
    const int eRow = rowBase + r;
    const int bk = tid >> 3, bc = (tid & 7) * 16;

    const int ln15 = lane & 15, hb = (lane >> 4) * 16;
    u32 ahB = smem_u32(Ahs) + 2 * ((wr * 32 + ln15) * AST) + hb;
    u32 alB = smem_u32(Als) + 2 * ((wr * 32 + ln15) * AST) + hb;
    u32 bhB = smem_u32(Bhs) + 2 * (ln15 * BST + wc * 64) + hb;
    u32 blB = smem_u32(Bls) + 2 * (ln15 * BST + wc * 64) + hb;

    float acc[2][8][4];
#pragma unroll
    for (int i = 0; i < 2; i++)
#pragma unroll
        for (int j = 0; j < 8; j++)
#pragma unroll
            for (int k = 0; k < 4; k++) acc[i][j][k] = 0.f;

    for (int k0 = 0; k0 < HID; k0 += 32) {
        float4 af[4], bf[4];
        const float4* ap4 = (const float4*)(g_h2 + (size_t)eRow * HID + k0 + kh);
        const float4* bp4 = (const float4*)(w3 + (size_t)(k0 + bk) * W3N + nBase + bc);
#pragma unroll
        for (int j = 0; j < 4; j++) { af[j] = ap4[j]; bf[j] = bp4[j]; }
        __syncthreads();
        stage_a16(Ahs, Als, r, kh, af);
        stage_b16(Bhs, Bls, bk, bc, bf);
        __syncthreads();
        compute_iter(ahB, alB, bhB, blB, acc);
    }
    // bias epilogue, fp32 store
    int gid = lane >> 2, q = lane & 3;
#pragma unroll
    for (int mt = 0; mt < 2; mt++)
#pragma unroll
        for (int sub = 0; sub < 2; sub++) {
            int rl = wr * 32 + mt * 16 + sub * 8 + gid;
            float* op = g_x0 + (size_t)(rowBase + rl) * W3N + nBase;
#pragma unroll
            for (int nt = 0; nt < 8; nt++) {
                int col = wc * 64 + nt * 8 + q * 2;
                float v0 = acc[mt][nt][sub * 2] + b3[nBase + col];
                float v1 = acc[mt][nt][sub * 2 + 1] + b3[nBase + col + 1];
                *(float2*)(op + col) = make_float2(v0, v1);
            }
        }
}

// ---------------- per-node rotate + reduce (f32x2, gathered dup weights) ----
__global__ __launch_bounds__(256) void k_node(
    const float* __restrict__ wig, float* __restrict__ out)
{
    __shared__ __align__(16) ull   Wg2[NGATH];
    __shared__ __align__(16) float Xs[M0C * CCH];
    const int tid = threadIdx.x;
    const int n = blockIdx.x;
    const int c4 = (tid & 31) << 2;
    const int rg = tid >> 5;
    const int row0 = rg * 7;

    const int beg = g_off[n];
    const int end = g_off[n + 1];

    const int gi0 = tid;
    const int gi1 = tid + 256;
    const int widx0 = g_wigidx[gi0 < NGATH ? gi0 : 0];
    const int widx1 = (gi1 < NGATH) ? g_wigidx[gi1] : 0;

    ull acc2[7][2];
#pragma unroll
    for (int r = 0; r < 7; r++) { acc2[r][0] = 0ull; acc2[r][1] = 0ull; }

    for (int ii = beg; ii < end; ii++) {
        int e = g_edges[ii];
        const float* wp = wig + (size_t)e * WROW;
        if (gi0 < NGATH) Wg2[gi0] = dup2(wp[widx0]);
        if (gi1 < NGATH) Wg2[gi1] = dup2(wp[widx1]);
        const float4* xp4 = (const float4*)(g_x0 + (size_t)e * W3N);
        if (tid < (M0C * CCH) / 4) ((float4*)Xs)[tid] = xp4[tid];
        __syncthreads();

        ull xa[M0C], xb[M0C];
#pragma unroll
        for (int m = 0; m < M0C; m++) {
            ulonglong2 xp = *(const ulonglong2*)&Xs[m * CCH + c4];
            xa[m] = xp.x; xb[m] = xp.y;
        }
#pragma unroll
        for (int r = 0; r < 7; r++) {
            int row = row0 + r;
            if (row < NSPH) {
#pragma unroll
                for (int m = 0; m < M0C; m++) {
                    ull w2 = Wg2[row * M0C + m];
                    FMA2(acc2[r][0], w2, xa[m]);
                    FMA2(acc2[r][1], w2, xb[m]);
                }
            }
        }
        __syncthreads();
    }

    const float sc = (float)(1.0 / 23.395238876342773);
#pragma unroll
    for (int r = 0; r < 7; r++) {
        int row = row0 + r;
        if (row < NSPH) {
            float v0, v1, v2, v3;
            unpk(acc2[r][0], v0, v1);
            unpk(acc2[r][1], v2, v3);
            float* op = out + (size_t)n * (NSPH * CCH) + row * CCH + c4;
            *(float4*)op = make_float4(v0 * sc, v1 * sc, v2 * sc, v3 * sc);
        }
    }
}

// ---------------- launch ----------------
extern "C" void kernel_launch(void* const* d_in, const int* in_sizes, int n_in,
                              void* d_out, int out_size)
{
    const int*   an   = (const int*)d_in[0];
    const float* ed   = (const float*)d_in[1];
    const int*   eidx = (const int*)d_in[2];
    const float* srcT = (const float*)d_in[3];
    const float* tgtT = (const float*)d_in[4];
    const float* w1   = (const float*)d_in[5];
    const float* b1   = (const float*)d_in[6];
    const float* g1   = (const float*)d_in[7];
    const float* be1  = (const float*)d_in[8];
    const float* w2   = (const float*)d_in[9];
    const float* b2   = (const float*)d_in[10];
    const float* g2   = (const float*)d_in[11];
    const float* be2  = (const float*)d_in[12];
    const float* w3   = (const float*)d_in[13];
    const float* b3   = (const float*)d_in[14];
    const float* tom  = (const float*)d_in[15];
    const float* wig  = (const float*)d_in[16];
    float* out = (float*)d_out;

    k_zero<<<(NODES + 255) / 256, 256>>>();
    k_hist<<<(E_NUM + 255) / 256, 256>>>(eidx);
    k_prep<<<1, 256>>>(tom);
    k_scatter<<<(E_NUM + 255) / 256, 256>>>(eidx);
    k_mgemm1<<<E_NUM / 128, 256>>>(an, ed, eidx, srcT, tgtT, w1, b1, g1, be1);
    k_mgemm2<<<E_NUM / 128, 256>>>(w2, b2, g2, be2);
    k_mgemm3<<<dim3(W3N / 128, E_NUM / 128), 256>>>(w3, b3);
    k_node<<<NODES, 256>>>(wig, out);
}